// round 16
// baseline (speedup 1.0000x reference)
#include <cuda_runtime.h>
#include <cuda_fp16.h>
#include <math.h>
#include <stdint.h>

// ---------------- problem constants ----------------
#define B_SZ   512
#define SEQ    102
#define EMB    256
#define NH     16
#define HD     16
#define FFD    1024
#define NLAYER 3
#define KSZ    50
#define PSZ    1000
#define MTOK   (B_SZ*SEQ)      // 52224 tokens
#define OUTW   ((PSZ+1)*2)     // 2002
#define QKVW   (3*EMB)         // 768

#define NSM    148
#define GEMM_GRID (2*NSM)      // persistent CTAs (2 per SM)

typedef unsigned long long ull;

// ---------------- device scratch (static; no allocs allowed) ----------------
__device__ __half g_QKVh[MTOK*QKVW];
__device__ __half g_Xh  [MTOK*EMB];
__device__ __half g_Oh  [MTOK*EMB];
__device__ __half g_X1h [MTOK*EMB];
__device__ __half g_Hh  [MTOK*FFD];
#define WQKV_SZ (QKVW*EMB)
#define WC_SZ   (EMB*EMB)
#define W1_SZ   (FFD*EMB)
#define W2_SZ   (EMB*FFD)
#define WL_SZ   (WQKV_SZ + WC_SZ + W1_SZ + W2_SZ)
__device__ __half g_Wh[NLAYER*WL_SZ];

// ---------------- helpers ----------------
__device__ __forceinline__ uint32_t smem_u32(const void* p) {
    uint32_t a;
    asm("{ .reg .u64 t; cvta.to.shared.u64 t, %1; cvt.u32.u64 %0, t; }"
        : "=r"(a) : "l"(p));
    return a;
}
__device__ __forceinline__ void cp16(uint32_t dst, const void* src) {
    asm volatile("cp.async.cg.shared.global [%0], [%1], 16;" :: "r"(dst), "l"(src));
}
#define CP_COMMIT() asm volatile("cp.async.commit_group;" ::: "memory")
#define CP_WAIT1()  asm volatile("cp.async.wait_group 1;" ::: "memory")
#define CP_WAIT0()  asm volatile("cp.async.wait_group 0;" ::: "memory")

#define LDSM4(r, addr) \
    asm volatile("ldmatrix.sync.aligned.m8n8.x4.shared.b16 {%0,%1,%2,%3}, [%4];" \
        : "=r"((r)[0]), "=r"((r)[1]), "=r"((r)[2]), "=r"((r)[3]) : "r"(addr))

#define LDSM4T(r, addr) \
    asm volatile("ldmatrix.sync.aligned.m8n8.x4.trans.shared.b16 {%0,%1,%2,%3}, [%4];" \
        : "=r"((r)[0]), "=r"((r)[1]), "=r"((r)[2]), "=r"((r)[3]) : "r"(addr))

#define MMA16816(d, a, b) \
    asm volatile("mma.sync.aligned.m16n8k16.row.col.f32.f16.f16.f32 " \
        "{%0,%1,%2,%3}, {%4,%5,%6,%7}, {%8,%9}, {%0,%1,%2,%3};" \
        : "+f"((d)[0]), "+f"((d)[1]), "+f"((d)[2]), "+f"((d)[3]) \
        : "r"((a)[0]), "r"((a)[1]), "r"((a)[2]), "r"((a)[3]), \
          "r"((b)[0]), "r"((b)[1]))

__device__ __forceinline__ uint32_t pack_h2(float a, float b) {
    __half2 h = __floats2half2_rn(a, b);
    return *(uint32_t*)&h;
}

// ---------------- weight convert ----------------
__global__ void wconv4_kernel(const float* __restrict__ Wq, const float* __restrict__ Wk,
                              const float* __restrict__ Wv, const float* __restrict__ Wc,
                              __half* __restrict__ oh)
{
    int l   = blockIdx.z;
    int mat = blockIdx.y >> 3;
    int kt  = blockIdx.y & 7;
    const float* W = (mat == 0) ? Wq : (mat == 1) ? Wk : (mat == 2) ? Wv : Wc;
    W  += (size_t)l*EMB*EMB;
    __half* dst = oh + (size_t)l*WL_SZ + (size_t)mat*EMB*EMB;

    __shared__ float tile[32][33];
    int n0 = blockIdx.x*32, k0 = kt*32;
    int tx = threadIdx.x, ty = threadIdx.y;  // 32 x 8
    #pragma unroll
    for (int i = ty; i < 32; i += 8)
        tile[i][tx] = W[(size_t)(k0+i)*EMB + n0 + tx];
    __syncthreads();
    #pragma unroll
    for (int i = ty; i < 32; i += 8)
        dst[(size_t)(n0+i)*EMB + k0 + tx] = __float2half_rn(tile[tx][i]);
}

__global__ void wconv_kernel(const float* __restrict__ W,
                             __half* __restrict__ oh,
                             int K, int N, size_t wstride, size_t ostride)
{
    int l = blockIdx.z;
    W  += (size_t)l*wstride;
    oh += (size_t)l*ostride;
    __shared__ float tile[32][33];
    int n0 = blockIdx.x*32, k0 = blockIdx.y*32;
    int tx = threadIdx.x, ty = threadIdx.y;  // 32 x 8
    #pragma unroll
    for (int i = ty; i < 32; i += 8)
        tile[i][tx] = W[(size_t)(k0+i)*N + n0 + tx];
    __syncthreads();
    #pragma unroll
    for (int i = ty; i < 32; i += 8)
        oh[(size_t)(n0+i)*K + k0 + tx] = __float2half_rn(tile[tx][i]);
}

// ---------------- build: copies + 2 GEMVs merged (branch on blockIdx.x) ----------------
#define COPY_BLKS 4096
__global__ __launch_bounds__(256) void build2_kernel(
    const float* __restrict__ x,
    const float* __restrict__ Wnv, const float* __restrict__ bnv,
    const float* __restrict__ Wv,  const float* __restrict__ bv,
    __half* __restrict__ Xh)
{
    const int t = threadIdx.x;
    if (blockIdx.x < COPY_BLKS) {
        const int total = B_SZ*100*(EMB/4);   // float4 units
        for (int i = blockIdx.x*256 + t; i < total; i += COPY_BLKS*256) {
            int c4    = (i & 63) << 2;
            int rowid = i >> 6;
            int b = rowid / 100;
            int r = rowid - b*100;
            int src = (r < 50) ? r : r + 1;
            int dst = src + 1;
            const float4 v = *(const float4*)(x + ((size_t)b*SEQ + src)*EMB + c4);
            __half* o = Xh + ((size_t)b*SEQ + dst)*EMB + c4;
            *(__half2*)(o)     = __floats2half2_rn(v.x, v.y);
            *(__half2*)(o + 2) = __floats2half2_rn(v.z, v.w);
        }
    } else {
        int gid = blockIdx.x - COPY_BLKS;     // 0..1023
        int b = gid >> 1, which = gid & 1;
        __shared__ float xs[EMB];
        const float* src = x + ((size_t)b*SEQ + (which ? 101 : 50))*EMB;
        const float* W   = which ? Wv : Wnv;
        const float* bb  = which ? bv : bnv;
        xs[t] = src[t];
        __syncthreads();
        float acc = bb[t];
        #pragma unroll 8
        for (int k = 0; k < EMB; k++) acc = fmaf(xs[k], W[k*EMB + t], acc);
        Xh[((size_t)b*SEQ + (which ? 51 : 0))*EMB + t] = __float2half_rn(acc);
    }
}

// ================= persistent HMMA fp16 GEMM =================
// 128x128 tile, K-chunk 64, 3-stage cp.async; 296 CTAs loop over tiles.
#define PITCH 72
#define A_ST  (128*PITCH)
#define B_ST  (128*PITCH)
#define NSTG  3
#define AB0   (NSTG*A_ST*2)
#define GEMM_SMEM (NSTG*(A_ST + B_ST)*2)  // 110592 bytes

__global__ __launch_bounds__(256, 2) void gemm_mma(
    const __half* __restrict__ Ah, const __half* __restrict__ Bh,
    const float* __restrict__ bias, const __half* __restrict__ res,
    __half* __restrict__ Ch,
    int M, int N, int K, int do_relu)
{
    extern __shared__ __align__(16) __half sm[];
    const uint32_t uBase = smem_u32(sm);

    const int t    = threadIdx.x;
    const int lane = t & 31;
    const int wid  = t >> 5;
    const int wm   = wid & 3;
    const int wn   = wid >> 2;

    const int ntn = N >> 7;              // N tiles
    const int ntiles = (M >> 7) * ntn;
    const int nchunks = K >> 6;

    for (int tile = blockIdx.x; tile < ntiles; tile += gridDim.x) {
        const int bm = (tile / ntn) << 7;
        const int bn = (tile % ntn) << 7;

        float acc[2][8][4];
        #pragma unroll
        for (int mt = 0; mt < 2; mt++)
            #pragma unroll
            for (int nt = 0; nt < 8; nt++)
                #pragma unroll
                for (int i = 0; i < 4; i++) acc[mt][nt][i] = 0.f;

        auto load_stage = [&](int ck) {
            const int s  = ck % NSTG;
            const int k0 = ck << 6;
            #pragma unroll
            for (int i = 0; i < 4; i++) {
                int cid = t + i*256;
                int row = cid >> 3;
                int c8  = (cid & 7) << 3;
                cp16(uBase + (uint32_t)((s*128 + row)*PITCH + c8)*2,
                     Ah + (size_t)(bm + row)*K + k0 + c8);
            }
            #pragma unroll
            for (int i = 0; i < 4; i++) {
                int cid = t + i*256;
                int row = cid >> 3;
                int c8  = (cid & 7) << 3;
                cp16(uBase + AB0 + (uint32_t)((s*128 + row)*PITCH + c8)*2,
                     Bh + (size_t)(bn + row)*K + k0 + c8);
            }
        };

        __syncthreads();                 // all warps done with smem from prior tile
        load_stage(0); CP_COMMIT();
        if (nchunks > 1) { load_stage(1); CP_COMMIT(); }

        for (int ck = 0; ck < nchunks; ck++) {
            CP_WAIT1();
            __syncthreads();
            if (ck + 2 < nchunks) { load_stage(ck + 2); CP_COMMIT(); }
            else { CP_COMMIT(); }        // keep wait_group accounting uniform

            const int s = ck % NSTG;
            const uint32_t aBase = uBase + (uint32_t)(s*A_ST)*2;
            const uint32_t bBase = uBase + AB0 + (uint32_t)(s*B_ST)*2;

            #pragma unroll
            for (int ks = 0; ks < 4; ks++) {
                uint32_t ah[2][4], bh[8][2];
                const int kcol = ks*16 + ((lane >> 4) << 3);
                #pragma unroll
                for (int mt = 0; mt < 2; mt++) {
                    int row = wm*32 + mt*16 + (lane & 15);
                    LDSM4(ah[mt], aBase + (uint32_t)(row*PITCH + kcol)*2);
                }
                #pragma unroll
                for (int p = 0; p < 4; p++) {
                    int row = wn*64 + p*16 + (lane & 15);
                    uint32_t r4[4];
                    LDSM4(r4, bBase + (uint32_t)(row*PITCH + kcol)*2);
                    bh[2*p][0] = r4[0]; bh[2*p+1][0] = r4[1];
                    bh[2*p][1] = r4[2]; bh[2*p+1][1] = r4[3];
                }
                #pragma unroll
                for (int mt = 0; mt < 2; mt++)
                    #pragma unroll
                    for (int nt = 0; nt < 8; nt++)
                        MMA16816(acc[mt][nt], ah[mt], bh[nt]);
            }
        }
        CP_WAIT0();                      // drain empty tail groups

        // ---- epilogue ----
        const int rb = bm + wm*32;
        const int cb = bn + wn*64;
        const int lr = lane >> 2;
        const int lc = (lane & 3) << 1;
        #pragma unroll
        for (int mt = 0; mt < 2; mt++) {
            #pragma unroll
            for (int nt = 0; nt < 8; nt++) {
                int r0 = rb + mt*16 + lr;
                int r1 = r0 + 8;
                int cc = cb + nt*8 + lc;
                float2 v0 = make_float2(acc[mt][nt][0], acc[mt][nt][1]);
                float2 v1 = make_float2(acc[mt][nt][2], acc[mt][nt][3]);
                if (bias) {
                    float2 bb = *(const float2*)(bias + cc);
                    v0.x += bb.x; v0.y += bb.y; v1.x += bb.x; v1.y += bb.y;
                }
                if (res) {
                    float2 q0 = __half22float2(*(const __half2*)(res + (size_t)r0*N + cc));
                    float2 q1 = __half22float2(*(const __half2*)(res + (size_t)r1*N + cc));
                    v0.x += q0.x; v0.y += q0.y; v1.x += q1.x; v1.y += q1.y;
                }
                if (do_relu) {
                    v0.x = fmaxf(v0.x, 0.f); v0.y = fmaxf(v0.y, 0.f);
                    v1.x = fmaxf(v1.x, 0.f); v1.y = fmaxf(v1.y, 0.f);
                }
                *(__half2*)(Ch + (size_t)r0*N + cc) = __floats2half2_rn(v0.x, v0.y);
                *(__half2*)(Ch + (size_t)r1*N + cc) = __floats2half2_rn(v1.x, v1.y);
            }
        }
    }
}

// ================= tensor-core flash attention =================
#define APITCH 24

__device__ __forceinline__ uint32_t lds_addr(uint32_t base, int row0, int lane) {
    return base + (uint32_t)((row0 + (lane & 15))*(APITCH*2) + ((lane >> 4) << 4));
}

__global__ __launch_bounds__(128, 2) void attn_kernel(
    const __half* __restrict__ QKV, __half* __restrict__ Oh)
{
    const int b = blockIdx.x, h = blockIdx.y, t = threadIdx.x;
    const int lane = t & 31, wid = t >> 5;
    __shared__ __align__(16) __half sQ[128*APITCH];
    __shared__ __align__(16) __half sK[112*APITCH];
    __shared__ __align__(16) __half sV[112*APITCH];

    for (int i = t; i < 128*APITCH/2; i += 128) ((uint32_t*)sQ)[i] = 0;
    for (int i = t; i < 112*APITCH/2; i += 128) {
        ((uint32_t*)sK)[i] = 0;
        ((uint32_t*)sV)[i] = 0;
    }
    __syncthreads();

    const size_t rowb = (size_t)b*SEQ*QKVW;
    const int hc = h*HD;
    for (int idx = t; idx < SEQ*8; idx += 128) {
        int n = idx >> 3, j = idx & 7;
        const __half2* base = (const __half2*)(QKV + rowb + (size_t)n*QKVW + hc);
        ((__half2*)sQ)[n*(APITCH/2) + j] = base[j];
        ((__half2*)sK)[n*(APITCH/2) + j] = *((const __half2*)(QKV + rowb + (size_t)n*QKVW + EMB   + hc) + j);
        ((__half2*)sV)[n*(APITCH/2) + j] = *((const __half2*)(QKV + rowb + (size_t)n*QKVW + 2*EMB + hc) + j);
    }
    __syncthreads();

    const uint32_t uQ = smem_u32(sQ);
    const uint32_t uK = smem_u32(sK);
    const uint32_t uV = smem_u32(sV);

    float sc[2][14][4];
    #pragma unroll
    for (int mt = 0; mt < 2; mt++)
        #pragma unroll
        for (int nt = 0; nt < 14; nt++)
            #pragma unroll
            for (int i = 0; i < 4; i++) sc[mt][nt][i] = 0.f;

    uint32_t qa[2][4];
    #pragma unroll
    for (int mt = 0; mt < 2; mt++)
        LDSM4(qa[mt], lds_addr(uQ, wid*32 + mt*16, lane));

    uint32_t kb[14][2];
    #pragma unroll
    for (int p = 0; p < 7; p++) {
        uint32_t r4[4];
        LDSM4(r4, lds_addr(uK, p*16, lane));
        kb[2*p][0]   = r4[0]; kb[2*p][1]   = r4[2];
        kb[2*p+1][0] = r4[1]; kb[2*p+1][1] = r4[3];
    }
    #pragma unroll
    for (int mt = 0; mt < 2; mt++)
        #pragma unroll
        for (int nt = 0; nt < 14; nt++)
            MMA16816(sc[mt][nt], qa[mt], kb[nt]);

    #pragma unroll
    for (int mt = 0; mt < 2; mt++) {
        if ((lane & 3) == 3) {
            sc[mt][12][0] = -1e30f; sc[mt][12][1] = -1e30f;
            sc[mt][12][2] = -1e30f; sc[mt][12][3] = -1e30f;
        }
        #pragma unroll
        for (int i = 0; i < 4; i++) sc[mt][13][i] = -1e30f;
    }

    float invs[2][2];
    #pragma unroll
    for (int mt = 0; mt < 2; mt++) {
        float mxA = -1e30f, mxB = -1e30f;
        #pragma unroll
        for (int nt = 0; nt < 14; nt++) {
            mxA = fmaxf(mxA, fmaxf(sc[mt][nt][0], sc[mt][nt][1]));
            mxB = fmaxf(mxB, fmaxf(sc[mt][nt][2], sc[mt][nt][3]));
        }
        mxA = fmaxf(mxA, __shfl_xor_sync(0xffffffffu, mxA, 1));
        mxA = fmaxf(mxA, __shfl_xor_sync(0xffffffffu, mxA, 2));
        mxB = fmaxf(mxB, __shfl_xor_sync(0xffffffffu, mxB, 1));
        mxB = fmaxf(mxB, __shfl_xor_sync(0xffffffffu, mxB, 2));
        const float nA = -0.25f*mxA, nB = -0.25f*mxB;
        float sA = 0.f, sB = 0.f;
        #pragma unroll
        for (int nt = 0; nt < 14; nt++) {
            float p0 = __expf(fmaf(sc[mt][nt][0], 0.25f, nA));
            float p1 = __expf(fmaf(sc[mt][nt][1], 0.25f, nA));
            float p2 = __expf(fmaf(sc[mt][nt][2], 0.25f, nB));
            float p3 = __expf(fmaf(sc[mt][nt][3], 0.25f, nB));
            sc[mt][nt][0] = p0; sc[mt][nt][1] = p1;
            sc[mt][nt][2] = p2; sc[mt][nt][3] = p3;
            sA += p0 + p1; sB += p2 + p3;
        }
        sA += __shfl_xor_sync(0xffffffffu, sA, 1);
        sA += __shfl_xor_sync(0xffffffffu, sA, 2);
        sB += __shfl_xor_sync(0xffffffffu, sB, 1);
        sB += __shfl_xor_sync(0xffffffffu, sB, 2);
        invs[mt][0] = 1.f/sA;
        invs[mt][1] = 1.f/sB;
    }

    float oc[2][2][4];
    #pragma unroll
    for (int mt = 0; mt < 2; mt++)
        #pragma unroll
        for (int nt = 0; nt < 2; nt++)
            #pragma unroll
            for (int i = 0; i < 4; i++) oc[mt][nt][i] = 0.f;

    #pragma unroll
    for (int ks = 0; ks < 7; ks++) {
        uint32_t r4[4];
        LDSM4T(r4, lds_addr(uV, ks*16, lane));
        uint32_t vb0[2] = { r4[0], r4[1] };
        uint32_t vb1[2] = { r4[2], r4[3] };
        #pragma unroll
        for (int mt = 0; mt < 2; mt++) {
            uint32_t pa[4];
            pa[0] = pack_h2(sc[mt][2*ks  ][0], sc[mt][2*ks  ][1]);
            pa[1] = pack_h2(sc[mt][2*ks  ][2], sc[mt][2*ks  ][3]);
            pa[2] = pack_h2(sc[mt][2*ks+1][0], sc[mt][2*ks+1][1]);
            pa[3] = pack_h2(sc[mt][2*ks+1][2], sc[mt][2*ks+1][3]);
            MMA16816(oc[mt][0], pa, vb0);
            MMA16816(oc[mt][1], pa, vb1);
        }
    }

    #pragma unroll
    for (int mt = 0; mt < 2; mt++) {
        int r0 = wid*32 + mt*16 + (lane >> 2);
        int r1 = r0 + 8;
        #pragma unroll
        for (int nt = 0; nt < 2; nt++) {
            int col = hc + nt*8 + (lane & 3)*2;
            if (r0 < SEQ)
                *(__half2*)(Oh + ((size_t)b*SEQ + r0)*EMB + col) =
                    __floats2half2_rn(oc[mt][nt][0]*invs[mt][0],
                                      oc[mt][nt][1]*invs[mt][0]);
            if (r1 < SEQ)
                *(__half2*)(Oh + ((size_t)b*SEQ + r1)*EMB + col) =
                    __floats2half2_rn(oc[mt][nt][2]*invs[mt][1],
                                      oc[mt][nt][3]*invs[mt][1]);
        }
    }
}

// ---------------- final: logits (fp16 X) -> masked softmax -> scatter ----------------
__global__ __launch_bounds__(128) void final_kernel(
    const __half* __restrict__ Xh,  const float* __restrict__ Wf,
    const float* __restrict__ bf, const float* __restrict__ mask,
    const int* __restrict__ lastu, const int* __restrict__ depotu,
    float* __restrict__ out)
{
    int b = blockIdx.x, t = threadIdx.x;   // 128 threads
    __shared__ float lg[128];
    __shared__ float red[128];

    float acc = -INFINITY;
    if (t < SEQ) {
        const __half2* r2 = (const __half2*)(Xh + ((size_t)b*SEQ + t)*EMB);
        const float2*  w2 = (const float2*)Wf;
        float s = bf[0];
        #pragma unroll 32
        for (int k = 0; k < EMB/2; k++) {
            float2 a = __half22float2(r2[k]);
            float2 w = w2[k];
            s = fmaf(a.x, w.x, s); s = fmaf(a.y, w.y, s);
        }
        if (t >= 1 && t <= KSZ) s += mask[(size_t)b*KSZ + (t-1)];
        if (t == 0 || t == KSZ+1) s = -INFINITY;
        acc = s;
    }
    lg[t] = acc;
    __syncthreads();

    red[t] = lg[t];
    __syncthreads();
    #pragma unroll
    for (int s = 64; s > 0; s >>= 1) {
        if (t < s) red[t] = fmaxf(red[t], red[t+s]);
        __syncthreads();
    }
    float mx = red[0];
    __syncthreads();

    float e = 0.f;
    if (t < SEQ && t != 0 && t != KSZ+1) e = __expf(lg[t] - mx);
    red[t] = e;
    __syncthreads();
    #pragma unroll
    for (int s = 64; s > 0; s >>= 1) {
        if (t < s) red[t] += red[t+s];
        __syncthreads();
    }
    float inv = 1.f / red[0];
    __syncthreads();
    lg[t] = e * inv;
    __syncthreads();

    float* orow = out + (size_t)b*OUTW;
    for (int i = t; i < OUTW; i += 128) orow[i] = 1e-20f;
    __syncthreads();

    if (t < KSZ) {
        float p1 = lg[1 + t];
        float p2 = lg[KSZ + 2 + t];
        if (p1 <= 1e-5f) p1 += 1e-7f;
        if (p2 <= 1e-5f) p2 += 1e-7f;
        orow[lastu[(size_t)b*KSZ + t]] = p1;
        orow[(PSZ + 1) + depotu[(size_t)b*KSZ + t]] = p2;
    }
}

// ---------------- launch ----------------
extern "C" void kernel_launch(void* const* d_in, const int* in_sizes, int n_in,
                              void* d_out, int out_size)
{
    (void)in_sizes; (void)n_in; (void)out_size;
    const float* x    = (const float*)d_in[0];
    const float* mask = (const float*)d_in[1];
    const float* Wnv  = (const float*)d_in[2];
    const float* bnv  = (const float*)d_in[3];
    const float* Wv_  = (const float*)d_in[4];
    const float* bv   = (const float*)d_in[5];
    const float* Wq   = (const float*)d_in[6];
    const float* Wk   = (const float*)d_in[7];
    const float* Wvp  = (const float*)d_in[8];
    const float* Wc   = (const float*)d_in[9];
    const float* bc   = (const float*)d_in[10];
    const float* W1   = (const float*)d_in[11];
    const float* b1   = (const float*)d_in[12];
    const float* W2   = (const float*)d_in[13];
    const float* b2   = (const float*)d_in[14];
    const float* Wf   = (const float*)d_in[15];
    const float* bf   = (const float*)d_in[16];
    const int*  lastu = (const int*)d_in[17];
    const int* depotu = (const int*)d_in[18];

    __half *QKVh, *Xh, *Oh, *X1h, *Hh, *Wh;
    cudaGetSymbolAddress((void**)&QKVh, g_QKVh);
    cudaGetSymbolAddress((void**)&Xh,   g_Xh);
    cudaGetSymbolAddress((void**)&Oh,   g_Oh);
    cudaGetSymbolAddress((void**)&X1h,  g_X1h);
    cudaGetSymbolAddress((void**)&Hh,   g_Hh);
    cudaGetSymbolAddress((void**)&Wh,   g_Wh);

    cudaFuncSetAttribute(gemm_mma, cudaFuncAttributeMaxDynamicSharedMemorySize,
                         GEMM_SMEM);

    dim3 ct(32, 8);

    wconv4_kernel<<<dim3(EMB/32, 4*(EMB/32), NLAYER), ct>>>(Wq, Wk, Wvp, Wc, Wh);
    wconv_kernel<<<dim3(FFD/32, EMB/32, NLAYER), ct>>>(W1, Wh + WQKV_SZ + WC_SZ, EMB, FFD, (size_t)EMB*FFD, WL_SZ);
    wconv_kernel<<<dim3(EMB/32, FFD/32, NLAYER), ct>>>(W2, Wh + WQKV_SZ + WC_SZ + W1_SZ, FFD, EMB, (size_t)FFD*EMB, WL_SZ);

    build2_kernel<<<COPY_BLKS + 2*B_SZ, 256>>>(x, Wnv, bnv, Wv_, bv, Xh);

    for (int l = 0; l < NLAYER; l++) {
        const __half* wh   = Wh + (size_t)l*WL_SZ;
        const __half* wc_h = wh + WQKV_SZ;
        const __half* w1_h = wh + WQKV_SZ + WC_SZ;
        const __half* w2_h = wh + WQKV_SZ + WC_SZ + W1_SZ;
        const float* bcl = bc + (size_t)l*EMB;
        const float* b1l = b1 + (size_t)l*FFD;
        const float* b2l = b2 + (size_t)l*EMB;

        gemm_mma<<<GEMM_GRID, 256, GEMM_SMEM>>>(Xh, wh, nullptr, nullptr,
                                                QKVh, MTOK, QKVW, EMB, 0);
        attn_kernel<<<dim3(B_SZ, NH), 128>>>(QKVh, Oh);
        gemm_mma<<<GEMM_GRID, 256, GEMM_SMEM>>>(Oh, wc_h, bcl, Xh,
                                                X1h, MTOK, EMB, EMB, 0);
        gemm_mma<<<GEMM_GRID, 256, GEMM_SMEM>>>(X1h, w1_h, b1l, nullptr,
                                                Hh, MTOK, FFD, EMB, 1);
        gemm_mma<<<GEMM_GRID, 256, GEMM_SMEM>>>(Hh, w2_h, b2l, X1h,
                                                Xh, MTOK, EMB, FFD, 0);
    }

    final_kernel<<<B_SZ, 128>>>(Xh, Wf, bf, mask, lastu, depotu, (float*)d_out);
}

// round 17
// speedup vs baseline: 1.0636x; 1.0636x over previous
#include <cuda_runtime.h>
#include <cuda_fp16.h>
#include <math.h>
#include <stdint.h>

// ---------------- problem constants ----------------
#define B_SZ   512
#define SEQ    102
#define EMB    256
#define NH     16
#define HD     16
#define FFD    1024
#define NLAYER 3
#define KSZ    50
#define PSZ    1000
#define MTOK   (B_SZ*SEQ)      // 52224 tokens
#define OUTW   ((PSZ+1)*2)     // 2002
#define QKVW   (3*EMB)         // 768

typedef unsigned long long ull;

// ---------------- device scratch (static; no allocs allowed) ----------------
__device__ __half g_QKVh[MTOK*QKVW];
__device__ __half g_Xh  [MTOK*EMB];
__device__ __half g_Oh  [MTOK*EMB];
__device__ __half g_X1h [MTOK*EMB];
__device__ __half g_Hh  [MTOK*FFD];
#define WQKV_SZ (QKVW*EMB)
#define WC_SZ   (EMB*EMB)
#define W1_SZ   (FFD*EMB)
#define W2_SZ   (EMB*FFD)
#define WL_SZ   (WQKV_SZ + WC_SZ + W1_SZ + W2_SZ)
__device__ __half g_Wh[NLAYER*WL_SZ];

// ---------------- helpers ----------------
__device__ __forceinline__ uint32_t smem_u32(const void* p) {
    uint32_t a;
    asm("{ .reg .u64 t; cvta.to.shared.u64 t, %1; cvt.u32.u64 %0, t; }"
        : "=r"(a) : "l"(p));
    return a;
}
__device__ __forceinline__ void cp16(uint32_t dst, const void* src) {
    asm volatile("cp.async.cg.shared.global [%0], [%1], 16;" :: "r"(dst), "l"(src));
}
#define CP_COMMIT() asm volatile("cp.async.commit_group;" ::: "memory")
#define CP_WAIT1()  asm volatile("cp.async.wait_group 1;" ::: "memory")

#define LDSM4(r, addr) \
    asm volatile("ldmatrix.sync.aligned.m8n8.x4.shared.b16 {%0,%1,%2,%3}, [%4];" \
        : "=r"((r)[0]), "=r"((r)[1]), "=r"((r)[2]), "=r"((r)[3]) : "r"(addr))

#define LDSM4T(r, addr) \
    asm volatile("ldmatrix.sync.aligned.m8n8.x4.trans.shared.b16 {%0,%1,%2,%3}, [%4];" \
        : "=r"((r)[0]), "=r"((r)[1]), "=r"((r)[2]), "=r"((r)[3]) : "r"(addr))

#define MMA16816(d, a, b) \
    asm volatile("mma.sync.aligned.m16n8k16.row.col.f32.f16.f16.f32 " \
        "{%0,%1,%2,%3}, {%4,%5,%6,%7}, {%8,%9}, {%0,%1,%2,%3};" \
        : "+f"((d)[0]), "+f"((d)[1]), "+f"((d)[2]), "+f"((d)[3]) \
        : "r"((a)[0]), "r"((a)[1]), "r"((a)[2]), "r"((a)[3]), \
          "r"((b)[0]), "r"((b)[1]))

__device__ __forceinline__ uint32_t pack_h2(float a, float b) {
    __half2 h = __floats2half2_rn(a, b);
    return *(uint32_t*)&h;
}

// ---------------- weight convert: ALL matrices, one launch ----------------
// grid: (768, 1, NLAYER). Tile ids per layer:
//   [0,256):   Wq/Wk/Wv/Wc (mat = id>>6; 8x8 tiles each)
//   [256,512): W1 (K=EMB, N=FFD; 32 n-tiles x 8 k-tiles)
//   [512,768): W2 (K=FFD, N=EMB; 8 n-tiles x 32 k-tiles)
__global__ void wconv_all(const float* __restrict__ Wq, const float* __restrict__ Wk,
                          const float* __restrict__ Wv, const float* __restrict__ Wc,
                          const float* __restrict__ W1, const float* __restrict__ W2,
                          __half* __restrict__ oh)
{
    const int l  = blockIdx.z;
    const int id = blockIdx.x;
    const float* W;
    __half* dst;
    int K, N, n0, k0;
    if (id < 256) {
        int mat = id >> 6, r = id & 63;
        const float* Ws[4] = {Wq, Wk, Wv, Wc};
        W   = Ws[mat] + (size_t)l*EMB*EMB;
        dst = oh + (size_t)l*WL_SZ + (size_t)mat*EMB*EMB;
        K = EMB; N = EMB; n0 = (r >> 3)*32; k0 = (r & 7)*32;
    } else if (id < 512) {
        int r = id - 256;
        W   = W1 + (size_t)l*EMB*FFD;
        dst = oh + (size_t)l*WL_SZ + WQKV_SZ + WC_SZ;
        K = EMB; N = FFD; n0 = (r >> 3)*32; k0 = (r & 7)*32;
    } else {
        int r = id - 512;
        W   = W2 + (size_t)l*FFD*EMB;
        dst = oh + (size_t)l*WL_SZ + WQKV_SZ + WC_SZ + W1_SZ;
        K = FFD; N = EMB; n0 = (r >> 5)*32; k0 = (r & 31)*32;
    }

    __shared__ float tile[32][33];
    int tx = threadIdx.x, ty = threadIdx.y;  // 32 x 8
    #pragma unroll
    for (int i = ty; i < 32; i += 8)
        tile[i][tx] = W[(size_t)(k0+i)*N + n0 + tx];
    __syncthreads();
    #pragma unroll
    for (int i = ty; i < 32; i += 8)
        dst[(size_t)(n0+i)*K + k0 + tx] = __float2half_rn(tile[tx][i]);
}

// ---------------- build: copy part (grid-stride, fp32 -> fp16) ----------------
__global__ __launch_bounds__(256) void copy_kernel(
    const float* __restrict__ x, __half* __restrict__ Xh)
{
    const int total = B_SZ*100*(EMB/4);   // float4 units
    for (int i = blockIdx.x*256 + threadIdx.x; i < total; i += gridDim.x*256) {
        int c4    = (i & 63) << 2;
        int rowid = i >> 6;
        int b = rowid / 100;
        int r = rowid - b*100;
        int src = (r < 50) ? r : r + 1;
        int dst = src + 1;
        const float4 v = *(const float4*)(x + ((size_t)b*SEQ + src)*EMB + c4);
        __half* o = Xh + ((size_t)b*SEQ + dst)*EMB + c4;
        *(__half2*)(o)     = __floats2half2_rn(v.x, v.y);
        *(__half2*)(o + 2) = __floats2half2_rn(v.z, v.w);
    }
}

// ---------------- build: GEMV part (rows 0 and 51 per batch) ----------------
__global__ __launch_bounds__(256) void gemv_kernel(
    const float* __restrict__ x,
    const float* __restrict__ Wnv, const float* __restrict__ bnv,
    const float* __restrict__ Wv,  const float* __restrict__ bv,
    __half* __restrict__ Xh)
{
    int b = blockIdx.x, which = blockIdx.y, t = threadIdx.x;   // 256 threads
    __shared__ float xs[EMB];
    const float* src = x + ((size_t)b*SEQ + (which ? 101 : 50))*EMB;
    const float* W   = which ? Wv : Wnv;
    const float* bb  = which ? bv : bnv;
    xs[t] = src[t];
    __syncthreads();
    float acc = bb[t];
    #pragma unroll 8
    for (int k = 0; k < EMB; k++) acc = fmaf(xs[k], W[k*EMB + t], acc);
    Xh[((size_t)b*SEQ + (which ? 51 : 0))*EMB + t] = __float2half_rn(acc);
}

// ================= HMMA fp16 GEMM, 128x128 tile, K-chunk 64, 3-stage =================
#define PITCH 72
#define A_ST  (128*PITCH)
#define B_ST  (128*PITCH)
#define NSTG  3
#define AB0   (NSTG*A_ST*2)
#define GEMM_SMEM (NSTG*(A_ST + B_ST)*2)  // 110592 bytes

__global__ __launch_bounds__(256, 2) void gemm_mma(
    const __half* __restrict__ Ah, const __half* __restrict__ Bh,
    const float* __restrict__ bias, const __half* __restrict__ res,
    __half* __restrict__ Ch,
    int M, int N, int K, int do_relu)
{
    extern __shared__ __align__(16) __half sm[];
    const uint32_t uBase = smem_u32(sm);

    const int t    = threadIdx.x;
    const int lane = t & 31;
    const int wid  = t >> 5;
    const int wm   = wid & 3;
    const int wn   = wid >> 2;
    const int bm   = blockIdx.y * 128;
    const int bn   = blockIdx.x * 128;

    float acc[2][8][4];
    #pragma unroll
    for (int mt = 0; mt < 2; mt++)
        #pragma unroll
        for (int nt = 0; nt < 8; nt++)
            #pragma unroll
            for (int i = 0; i < 4; i++) acc[mt][nt][i] = 0.f;

    const int nchunks = K >> 6;

    auto load_stage = [&](int ck) {
        const int s  = ck % NSTG;
        const int k0 = ck << 6;
        #pragma unroll
        for (int i = 0; i < 4; i++) {
            int cid = t + i*256;
            int row = cid >> 3;
            int c8  = (cid & 7) << 3;
            cp16(uBase + (uint32_t)((s*128 + row)*PITCH + c8)*2,
                 Ah + (size_t)(bm + row)*K + k0 + c8);
        }
        #pragma unroll
        for (int i = 0; i < 4; i++) {
            int cid = t + i*256;
            int row = cid >> 3;
            int c8  = (cid & 7) << 3;
            cp16(uBase + AB0 + (uint32_t)((s*128 + row)*PITCH + c8)*2,
                 Bh + (size_t)(bn + row)*K + k0 + c8);
        }
    };

    load_stage(0); CP_COMMIT();
    if (nchunks > 1) { load_stage(1); CP_COMMIT(); }

    for (int ck = 0; ck < nchunks; ck++) {
        CP_WAIT1();
        __syncthreads();
        if (ck + 2 < nchunks) { load_stage(ck + 2); CP_COMMIT(); }
        else { CP_COMMIT(); }   // empty groups keep wait_group accounting correct

        const int s = ck % NSTG;
        const uint32_t aBase = uBase + (uint32_t)(s*A_ST)*2;
        const uint32_t bBase = uBase + AB0 + (uint32_t)(s*B_ST)*2;

        #pragma unroll
        for (int ks = 0; ks < 4; ks++) {
            uint32_t ah[2][4], bh[8][2];
            const int kcol = ks*16 + ((lane >> 4) << 3);
            #pragma unroll
            for (int mt = 0; mt < 2; mt++) {
                int row = wm*32 + mt*16 + (lane & 15);
                LDSM4(ah[mt], aBase + (uint32_t)(row*PITCH + kcol)*2);
            }
            #pragma unroll
            for (int p = 0; p < 4; p++) {
                int row = wn*64 + p*16 + (lane & 15);
                uint32_t r4[4];
                LDSM4(r4, bBase + (uint32_t)(row*PITCH + kcol)*2);
                bh[2*p][0] = r4[0]; bh[2*p+1][0] = r4[1];
                bh[2*p][1] = r4[2]; bh[2*p+1][1] = r4[3];
            }
            #pragma unroll
            for (int mt = 0; mt < 2; mt++)
                #pragma unroll
                for (int nt = 0; nt < 8; nt++)
                    MMA16816(acc[mt][nt], ah[mt], bh[nt]);
        }
    }

    // ---- epilogue (all-fp16 out) ----
    const int rb = bm + wm*32;
    const int cb = bn + wn*64;
    const int lr = lane >> 2;
    const int lc = (lane & 3) << 1;
    #pragma unroll
    for (int mt = 0; mt < 2; mt++) {
        #pragma unroll
        for (int nt = 0; nt < 8; nt++) {
            int r0 = rb + mt*16 + lr;
            int r1 = r0 + 8;
            int cc = cb + nt*8 + lc;
            float2 v0 = make_float2(acc[mt][nt][0], acc[mt][nt][1]);
            float2 v1 = make_float2(acc[mt][nt][2], acc[mt][nt][3]);
            if (bias) {
                float2 bb = *(const float2*)(bias + cc);
                v0.x += bb.x; v0.y += bb.y; v1.x += bb.x; v1.y += bb.y;
            }
            if (res) {
                float2 q0 = __half22float2(*(const __half2*)(res + (size_t)r0*N + cc));
                float2 q1 = __half22float2(*(const __half2*)(res + (size_t)r1*N + cc));
                v0.x += q0.x; v0.y += q0.y; v1.x += q1.x; v1.y += q1.y;
            }
            if (do_relu) {
                v0.x = fmaxf(v0.x, 0.f); v0.y = fmaxf(v0.y, 0.f);
                v1.x = fmaxf(v1.x, 0.f); v1.y = fmaxf(v1.y, 0.f);
            }
            *(__half2*)(Ch + (size_t)r0*N + cc) = __floats2half2_rn(v0.x, v0.y);
            *(__half2*)(Ch + (size_t)r1*N + cc) = __floats2half2_rn(v1.x, v1.y);
        }
    }
}

// ================= tensor-core flash attention =================
#define APITCH 24

__device__ __forceinline__ uint32_t lds_addr(uint32_t base, int row0, int lane) {
    return base + (uint32_t)((row0 + (lane & 15))*(APITCH*2) + ((lane >> 4) << 4));
}

__global__ __launch_bounds__(128, 2) void attn_kernel(
    const __half* __restrict__ QKV, __half* __restrict__ Oh)
{
    const int b = blockIdx.x, h = blockIdx.y, t = threadIdx.x;
    const int lane = t & 31, wid = t >> 5;
    __shared__ __align__(16) __half sQ[128*APITCH];
    __shared__ __align__(16) __half sK[112*APITCH];
    __shared__ __align__(16) __half sV[112*APITCH];

    for (int i = t; i < 128*APITCH/2; i += 128) ((uint32_t*)sQ)[i] = 0;
    for (int i = t; i < 112*APITCH/2; i += 128) {
        ((uint32_t*)sK)[i] = 0;
        ((uint32_t*)sV)[i] = 0;
    }
    __syncthreads();

    const size_t rowb = (size_t)b*SEQ*QKVW;
    const int hc = h*HD;
    for (int idx = t; idx < SEQ*8; idx += 128) {
        int n = idx >> 3, j = idx & 7;
        const __half2* base = (const __half2*)(QKV + rowb + (size_t)n*QKVW + hc);
        ((__half2*)sQ)[n*(APITCH/2) + j] = base[j];
        ((__half2*)sK)[n*(APITCH/2) + j] = *((const __half2*)(QKV + rowb + (size_t)n*QKVW + EMB   + hc) + j);
        ((__half2*)sV)[n*(APITCH/2) + j] = *((const __half2*)(QKV + rowb + (size_t)n*QKVW + 2*EMB + hc) + j);
    }
    __syncthreads();

    const uint32_t uQ = smem_u32(sQ);
    const uint32_t uK = smem_u32(sK);
    const uint32_t uV = smem_u32(sV);

    float sc[2][14][4];
    #pragma unroll
    for (int mt = 0; mt < 2; mt++)
        #pragma unroll
        for (int nt = 0; nt < 14; nt++)
            #pragma unroll
            for (int i = 0; i < 4; i++) sc[mt][nt][i] = 0.f;

    uint32_t qa[2][4];
    #pragma unroll
    for (int mt = 0; mt < 2; mt++)
        LDSM4(qa[mt], lds_addr(uQ, wid*32 + mt*16, lane));

    uint32_t kb[14][2];
    #pragma unroll
    for (int p = 0; p < 7; p++) {
        uint32_t r4[4];
        LDSM4(r4, lds_addr(uK, p*16, lane));
        kb[2*p][0]   = r4[0]; kb[2*p][1]   = r4[2];
        kb[2*p+1][0] = r4[1]; kb[2*p+1][1] = r4[3];
    }
    #pragma unroll
    for (int mt = 0; mt < 2; mt++)
        #pragma unroll
        for (int nt = 0; nt < 14; nt++)
            MMA16816(sc[mt][nt], qa[mt], kb[nt]);

    #pragma unroll
    for (int mt = 0; mt < 2; mt++) {
        if ((lane & 3) == 3) {
            sc[mt][12][0] = -1e30f; sc[mt][12][1] = -1e30f;
            sc[mt][12][2] = -1e30f; sc[mt][12][3] = -1e30f;
        }
        #pragma unroll
        for (int i = 0; i < 4; i++) sc[mt][13][i] = -1e30f;
    }

    float invs[2][2];
    #pragma unroll
    for (int mt = 0; mt < 2; mt++) {
        float mxA = -1e30f, mxB = -1e30f;
        #pragma unroll
        for (int nt = 0; nt < 14; nt++) {
            mxA = fmaxf(mxA, fmaxf(sc[mt][nt][0], sc[mt][nt][1]));
            mxB = fmaxf(mxB, fmaxf(sc[mt][nt][2], sc[mt][nt][3]));
        }
        mxA = fmaxf(mxA, __shfl_xor_sync(0xffffffffu, mxA, 1));
        mxA = fmaxf(mxA, __shfl_xor_sync(0xffffffffu, mxA, 2));
        mxB = fmaxf(mxB, __shfl_xor_sync(0xffffffffu, mxB, 1));
        mxB = fmaxf(mxB, __shfl_xor_sync(0xffffffffu, mxB, 2));
        const float nA = -0.25f*mxA, nB = -0.25f*mxB;
        float sA = 0.f, sB = 0.f;
        #pragma unroll
        for (int nt = 0; nt < 14; nt++) {
            float p0 = __expf(fmaf(sc[mt][nt][0], 0.25f, nA));
            float p1 = __expf(fmaf(sc[mt][nt][1], 0.25f, nA));
            float p2 = __expf(fmaf(sc[mt][nt][2], 0.25f, nB));
            float p3 = __expf(fmaf(sc[mt][nt][3], 0.25f, nB));
            sc[mt][nt][0] = p0; sc[mt][nt][1] = p1;
            sc[mt][nt][2] = p2; sc[mt][nt][3] = p3;
            sA += p0 + p1; sB += p2 + p3;
        }
        sA += __shfl_xor_sync(0xffffffffu, sA, 1);
        sA += __shfl_xor_sync(0xffffffffu, sA, 2);
        sB += __shfl_xor_sync(0xffffffffu, sB, 1);
        sB += __shfl_xor_sync(0xffffffffu, sB, 2);
        invs[mt][0] = 1.f/sA;
        invs[mt][1] = 1.f/sB;
    }

    float oc[2][2][4];
    #pragma unroll
    for (int mt = 0; mt < 2; mt++)
        #pragma unroll
        for (int nt = 0; nt < 2; nt++)
            #pragma unroll
            for (int i = 0; i < 4; i++) oc[mt][nt][i] = 0.f;

    #pragma unroll
    for (int ks = 0; ks < 7; ks++) {
        uint32_t r4[4];
        LDSM4T(r4, lds_addr(uV, ks*16, lane));
        uint32_t vb0[2] = { r4[0], r4[1] };
        uint32_t vb1[2] = { r4[2], r4[3] };
        #pragma unroll
        for (int mt = 0; mt < 2; mt++) {
            uint32_t pa[4];
            pa[0] = pack_h2(sc[mt][2*ks  ][0], sc[mt][2*ks  ][1]);
            pa[1] = pack_h2(sc[mt][2*ks  ][2], sc[mt][2*ks  ][3]);
            pa[2] = pack_h2(sc[mt][2*ks+1][0], sc[mt][2*ks+1][1]);
            pa[3] = pack_h2(sc[mt][2*ks+1][2], sc[mt][2*ks+1][3]);
            MMA16816(oc[mt][0], pa, vb0);
            MMA16816(oc[mt][1], pa, vb1);
        }
    }

    #pragma unroll
    for (int mt = 0; mt < 2; mt++) {
        int r0 = wid*32 + mt*16 + (lane >> 2);
        int r1 = r0 + 8;
        #pragma unroll
        for (int nt = 0; nt < 2; nt++) {
            int col = hc + nt*8 + (lane & 3)*2;
            if (r0 < SEQ)
                *(__half2*)(Oh + ((size_t)b*SEQ + r0)*EMB + col) =
                    __floats2half2_rn(oc[mt][nt][0]*invs[mt][0],
                                      oc[mt][nt][1]*invs[mt][0]);
            if (r1 < SEQ)
                *(__half2*)(Oh + ((size_t)b*SEQ + r1)*EMB + col) =
                    __floats2half2_rn(oc[mt][nt][2]*invs[mt][1],
                                      oc[mt][nt][3]*invs[mt][1]);
        }
    }
}

// ---------------- final: logits (fp16 X) -> masked softmax -> scatter ----------------
__global__ __launch_bounds__(128) void final_kernel(
    const __half* __restrict__ Xh,  const float* __restrict__ Wf,
    const float* __restrict__ bf, const float* __restrict__ mask,
    const int* __restrict__ lastu, const int* __restrict__ depotu,
    float* __restrict__ out)
{
    int b = blockIdx.x, t = threadIdx.x;   // 128 threads
    __shared__ float lg[128];
    __shared__ float red[128];

    float acc = -INFINITY;
    if (t < SEQ) {
        const __half2* r2 = (const __half2*)(Xh + ((size_t)b*SEQ + t)*EMB);
        const float2*  w2 = (const float2*)Wf;
        float s = bf[0];
        #pragma unroll 32
        for (int k = 0; k < EMB/2; k++) {
            float2 a = __half22float2(r2[k]);
            float2 w = w2[k];
            s = fmaf(a.x, w.x, s); s = fmaf(a.y, w.y, s);
        }
        if (t >= 1 && t <= KSZ) s += mask[(size_t)b*KSZ + (t-1)];
        if (t == 0 || t == KSZ+1) s = -INFINITY;
        acc = s;
    }
    lg[t] = acc;
    __syncthreads();

    red[t] = lg[t];
    __syncthreads();
    #pragma unroll
    for (int s = 64; s > 0; s >>= 1) {
        if (t < s) red[t] = fmaxf(red[t], red[t+s]);
        __syncthreads();
    }
    float mx = red[0];
    __syncthreads();

    float e = 0.f;
    if (t < SEQ && t != 0 && t != KSZ+1) e = __expf(lg[t] - mx);
    red[t] = e;
    __syncthreads();
    #pragma unroll
    for (int s = 64; s > 0; s >>= 1) {
        if (t < s) red[t] += red[t+s];
        __syncthreads();
    }
    float inv = 1.f / red[0];
    __syncthreads();
    lg[t] = e * inv;
    __syncthreads();

    float* orow = out + (size_t)b*OUTW;
    for (int i = t; i < OUTW; i += 128) orow[i] = 1e-20f;
    __syncthreads();

    if (t < KSZ) {
        float p1 = lg[1 + t];
        float p2 = lg[KSZ + 2 + t];
        if (p1 <= 1e-5f) p1 += 1e-7f;
        if (p2 <= 1e-5f) p2 += 1e-7f;
        orow[lastu[(size_t)b*KSZ + t]] = p1;
        orow[(PSZ + 1) + depotu[(size_t)b*KSZ + t]] = p2;
    }
}

// ---------------- launch ----------------
extern "C" void kernel_launch(void* const* d_in, const int* in_sizes, int n_in,
                              void* d_out, int out_size)
{
    (void)in_sizes; (void)n_in; (void)out_size;
    const float* x    = (const float*)d_in[0];
    const float* mask = (const float*)d_in[1];
    const float* Wnv  = (const float*)d_in[2];
    const float* bnv  = (const float*)d_in[3];
    const float* Wv_  = (const float*)d_in[4];
    const float* bv   = (const float*)d_in[5];
    const float* Wq   = (const float*)d_in[6];
    const float* Wk   = (const float*)d_in[7];
    const float* Wvp  = (const float*)d_in[8];
    const float* Wc   = (const float*)d_in[9];
    const float* bc   = (const float*)d_in[10];
    const float* W1   = (const float*)d_in[11];
    const float* b1   = (const float*)d_in[12];
    const float* W2   = (const float*)d_in[13];
    const float* b2   = (const float*)d_in[14];
    const float* Wf   = (const float*)d_in[15];
    const float* bf   = (const float*)d_in[16];
    const int*  lastu = (const int*)d_in[17];
    const int* depotu = (const int*)d_in[18];

    __half *QKVh, *Xh, *Oh, *X1h, *Hh, *Wh;
    cudaGetSymbolAddress((void**)&QKVh, g_QKVh);
    cudaGetSymbolAddress((void**)&Xh,   g_Xh);
    cudaGetSymbolAddress((void**)&Oh,   g_Oh);
    cudaGetSymbolAddress((void**)&X1h,  g_X1h);
    cudaGetSymbolAddress((void**)&Hh,   g_Hh);
    cudaGetSymbolAddress((void**)&Wh,   g_Wh);

    cudaFuncSetAttribute(gemm_mma, cudaFuncAttributeMaxDynamicSharedMemorySize,
                         GEMM_SMEM);

    dim3 ct(32, 8);
    dim3 gQKV(QKVW/128, MTOK/128);   // (6, 408)
    dim3 gE  (EMB/128,  MTOK/128);   // (2, 408)
    dim3 gF  (FFD/128,  MTOK/128);   // (8, 408)

    // all weight conversions in ONE launch
    wconv_all<<<dim3(768, 1, NLAYER), ct>>>(Wq, Wk, Wvp, Wc, W1, W2, Wh);

    copy_kernel<<<4096, 256>>>(x, Xh);
    gemv_kernel<<<dim3(B_SZ, 2), 256>>>(x, Wnv, bnv, Wv_, bv, Xh);

    for (int l = 0; l < NLAYER; l++) {
        const __half* wh   = Wh + (size_t)l*WL_SZ;
        const __half* wc_h = wh + WQKV_SZ;
        const __half* w1_h = wh + WQKV_SZ + WC_SZ;
        const __half* w2_h = wh + WQKV_SZ + WC_SZ + W1_SZ;
        const float* bcl = bc + (size_t)l*EMB;
        const float* b1l = b1 + (size_t)l*FFD;
        const float* b2l = b2 + (size_t)l*EMB;

        gemm_mma<<<gQKV, 256, GEMM_SMEM>>>(Xh, wh, nullptr, nullptr,
                                           QKVh, MTOK, QKVW, EMB, 0);
        attn_kernel<<<dim3(B_SZ, NH), 128>>>(QKVh, Oh);
        gemm_mma<<<gE, 256, GEMM_SMEM>>>(Oh, wc_h, bcl, Xh,
                                         X1h, MTOK, EMB, EMB, 0);
        gemm_mma<<<gF, 256, GEMM_SMEM>>>(X1h, w1_h, b1l, nullptr,
                                         Hh, MTOK, FFD, EMB, 1);
        gemm_mma<<<gE, 256, GEMM_SMEM>>>(Hh, w2_h, b2l, X1h,
                                         Xh, MTOK, EMB, FFD, 0);
    }

    final_kernel<<<B_SZ, 128>>>(Xh, Wf, bf, mask, lastu, depotu, (float*)d_out);
}